// round 9
// baseline (speedup 1.0000x reference)
#include <cuda_runtime.h>
#include <math_constants.h>

// Problem constants
#define BB   16
#define DD   1024
#define TT   4096
#define CDIM 8
#define CSZ  1024

#define NTHREADS 512
#define NG   8                     // groups = 2 warps each (warp-uniform)
#define SLOTS 64                   // thread slots per group
#define TV   2                     // t-columns per thread
#define TILE (SLOTS * TV)          // 128 t per block
#define DG   (DD / NG)             // 128 d per group
#define CG   (CSZ / NG)            // 128 codes per group
#define TILES_PER_B (TT / TILE)    // 32
#define GRID (BB * TILES_PER_B)    // 512 (2 waves at occ 2 -> phase mixing)

// Output layout (concatenated float32):
// out [B,D,T], commitment_loss [B], codebook_loss [B], indices [B,T], z_e [B,CD,T]
#define OFF_CL  (BB * DD * TT)
#define OFF_CB  (OFF_CL + BB)
#define OFF_IDX (OFF_CB + BB)
#define OFF_ZE  (OFF_IDX + BB * TT)

// Device-global scratch
__device__ float g_winT[DD * CDIM];   // in-proj weight transposed [d][k]
__device__ float g_wout[DD * CDIM];   // out-proj weight [d][k]
__device__ float g_cbn[CSZ * CDIM];   // normalized codebook [c][k]
__device__ float g_losspart[GRID];
__device__ unsigned int g_done;       // zero-init; self-resetting

// ---------------- f32x2 packed helpers ----------------
typedef unsigned long long u64;

__device__ __forceinline__ u64 pk(float lo, float hi) {
    u64 r; asm("mov.b64 %0, {%1, %2};" : "=l"(r) : "f"(lo), "f"(hi)); return r;
}
__device__ __forceinline__ void upk(float& lo, float& hi, u64 v) {
    asm("mov.b64 {%0, %1}, %2;" : "=f"(lo), "=f"(hi) : "l"(v));
}
__device__ __forceinline__ u64 f2(u64 a, u64 b, u64 c) {
    u64 d; asm("fma.rn.f32x2 %0, %1, %2, %3;" : "=l"(d) : "l"(a), "l"(b), "l"(c)); return d;
}
__device__ __forceinline__ u64 a2(u64 a, u64 b) {
    u64 d; asm("add.rn.f32x2 %0, %1, %2;" : "=l"(d) : "l"(a), "l"(b)); return d;
}

// ---------------------------------------------------------------------------
// Prep: blocks 0..7 -> weight-norm in_proj row o (norm over D), transpose.
//       blocks 8..11 -> weight-norm out_proj rows + l2-normalized codebook.
// ---------------------------------------------------------------------------
__global__ void vq_prep(const float* __restrict__ ipv, const float* __restrict__ ipg,
                        const float* __restrict__ opv, const float* __restrict__ opg,
                        const float* __restrict__ cb) {
    if (blockIdx.x < CDIM) {
        int o = blockIdx.x;
        __shared__ float red[256];
        float s = 0.f;
        for (int d = threadIdx.x; d < DD; d += blockDim.x) {
            float x = ipv[o * DD + d];
            s = fmaf(x, x, s);
        }
        red[threadIdx.x] = s;
        __syncthreads();
        for (int off = 128; off > 0; off >>= 1) {
            if (threadIdx.x < off) red[threadIdx.x] += red[threadIdx.x + off];
            __syncthreads();
        }
        float scale = ipg[o] / sqrtf(red[0]);
        for (int d = threadIdx.x; d < DD; d += blockDim.x)
            g_winT[d * CDIM + o] = ipv[o * DD + d] * scale;
    } else {
        int i = (blockIdx.x - CDIM) * 256 + threadIdx.x;
        if (i < DD) {
            float vv[CDIM];
            float s = 0.f;
#pragma unroll
            for (int c = 0; c < CDIM; c++) { vv[c] = opv[i * CDIM + c]; s = fmaf(vv[c], vv[c], s); }
            float sc = opg[i] / sqrtf(s);
#pragma unroll
            for (int c = 0; c < CDIM; c++) g_wout[i * CDIM + c] = vv[c] * sc;
        }
        if (i < CSZ) {
            float vv[CDIM];
            float s = 0.f;
#pragma unroll
            for (int k = 0; k < CDIM; k++) { vv[k] = cb[i * CDIM + k]; s = fmaf(vv[k], vv[k], s); }
            float inv = 1.f / fmaxf(sqrtf(s), 1e-12f);
#pragma unroll
            for (int k = 0; k < CDIM; k++) g_cbn[i * CDIM + k] = vv[k] * inv;
        }
    }
}

// Dynamic smem layout (bytes):
//   s_winT [0,      32768)
//   s_cbn  [32768,  65536)
//   s_wout [65536,  98304)
//   s_ex   [98304, 114688)  16 KB: 2-round partial exchange; later aliased:
//            [+0, +4K)  s_best [NG][TILE] floats
//            [+4K,+8K)  s_bi   [NG][TILE] ints
//            [+8K,+12K) s_bias [DD] floats
//   s_red  [114688, 114752)
// Total 114752 B/block -> 2 blocks/SM.
// ---------------------------------------------------------------------------
__global__ void __launch_bounds__(NTHREADS, 2)
vq_main(const float* __restrict__ z,
        const float* __restrict__ in_b,
        const float* __restrict__ out_b,
        const float* __restrict__ cb,
        float* __restrict__ out) {
    extern __shared__ __align__(16) char smem[];
    float* s_winT = (float*)smem;
    float* s_cbn  = (float*)(smem + 32768);
    float* s_wout = (float*)(smem + 65536);
    u64*   s_ex   = (u64*)(smem + 98304);
    float* s_best = (float*)(smem + 98304);
    int*   s_bi   = (int*)(smem + 98304 + 4096);
    float* s_bias = (float*)(smem + 98304 + 8192);
    float* s_red  = (float*)(smem + 114688);

    const int tid  = threadIdx.x;
    const int g    = tid >> 6;          // group 0..7 (uniform across its 2 warps)
    const int slot = tid & (SLOTS - 1); // 0..63
    const int blk  = blockIdx.x;
    const int b    = blk / TILES_PER_B;
    const int t0   = (blk % TILES_PER_B) * TILE + slot * TV;

    // ---- stage ALL tables once (96 KB) ----
    {
        const float4* w1 = (const float4*)g_winT;
        const float4* w2 = (const float4*)g_cbn;
        const float4* w3 = (const float4*)g_wout;
        float4* d1 = (float4*)s_winT;
        float4* d2 = (float4*)s_cbn;
        float4* d3 = (float4*)s_wout;
        for (int i = tid; i < DD * CDIM / 4; i += NTHREADS) {
            d1[i] = w1[i];
            d2[i] = w2[i];
            d3[i] = w3[i];
        }
    }
    __syncthreads();

    // ---- phase 1: partial z_e over this group's 128 d's, 2 columns ----
    u64 aA[4] = {0, 0, 0, 0};
    u64 aB[4] = {0, 0, 0, 0};
    {
        const float* zp = z + (size_t)b * (DD * TT) + (size_t)(g * DG) * TT + t0;
        const ulonglong2* wp = (const ulonglong2*)(s_winT + g * DG * CDIM);
#pragma unroll 8
        for (int d = 0; d < DG; d++) {
            float2 zv = __ldcs((const float2*)(zp + (size_t)d * TT));
            ulonglong2 w01 = wp[2 * d];        // warp-uniform LDS broadcast
            ulonglong2 w23 = wp[2 * d + 1];
            u64 za = pk(zv.x, zv.x);
            u64 zb = pk(zv.y, zv.y);
            aA[0] = f2(w01.x, za, aA[0]);  aB[0] = f2(w01.x, zb, aB[0]);
            aA[1] = f2(w01.y, za, aA[1]);  aB[1] = f2(w01.y, zb, aB[1]);
            aA[2] = f2(w23.x, za, aA[2]);  aB[2] = f2(w23.x, zb, aB[2]);
            aA[3] = f2(w23.y, za, aA[3]);  aB[3] = f2(w23.y, zb, aB[3]);
        }
    }

    // ---- 2-round partial exchange (16 KB buffer), combine ascending g ----
    u64 zeA[4], zeB[4];
    const float2* bb = (const float2*)in_b;
#pragma unroll
    for (int r = 0; r < 2; r++) {
#pragma unroll
        for (int jj = 0; jj < 2; jj++) {
            s_ex[((jj * 2 + 0) * NG + g) * SLOTS + slot] = aA[2 * r + jj];
            s_ex[((jj * 2 + 1) * NG + g) * SLOTS + slot] = aB[2 * r + jj];
        }
        __syncthreads();
#pragma unroll
        for (int jj = 0; jj < 2; jj++) {
            int j = 2 * r + jj;
            float2 bj = __ldg(bb + j);
            u64 bp = pk(bj.x, bj.y);
            u64 sa = s_ex[((jj * 2 + 0) * NG + 0) * SLOTS + slot];
            u64 sb = s_ex[((jj * 2 + 1) * NG + 0) * SLOTS + slot];
#pragma unroll
            for (int gg = 1; gg < NG; gg++) {
                sa = a2(sa, s_ex[((jj * 2 + 0) * NG + gg) * SLOTS + slot]);
                sb = a2(sb, s_ex[((jj * 2 + 1) * NG + gg) * SLOTS + slot]);
            }
            zeA[j] = a2(sa, bp);
            zeB[j] = a2(sb, bp);
        }
        __syncthreads();   // reads complete before buffer reuse
    }

    // stage out-proj bias into freed exchange space (consumed in P3, ordered
    // by the pre-P3 argmax sync)
    for (int i = tid; i < DD; i += NTHREADS) s_bias[i] = __ldg(out_b + i);

    // write z_e [B, CD, T], spread across groups 0..3 (group j -> rows 2j,2j+1)
    if (g < 4) {
        int j = g;
        float a0, a1, b0, b1;
        upk(a0, a1, zeA[j]);
        upk(b0, b1, zeB[j]);
        float* zeo = out + OFF_ZE + (size_t)b * (CDIM * TT) + t0;
        __stcs((float2*)(zeo + (size_t)(2 * j) * TT),     make_float2(a0, b0));
        __stcs((float2*)(zeo + (size_t)(2 * j + 1) * TT), make_float2(a1, b1));
    }

    // ---- phase 2: argmax over this group's 128 codes, both columns ----
    float bestA = -CUDART_INF_F, bestB = -CUDART_INF_F;
    int biA = 0, biB = 0;
    {
        const float* cbase = s_cbn + g * CG * CDIM;
#pragma unroll 4
        for (int cc = 0; cc < CG; cc++) {
            const ulonglong2* r = (const ulonglong2*)(cbase + cc * CDIM);
            ulonglong2 c01 = r[0];   // warp-uniform LDS broadcast
            ulonglong2 c23 = r[1];
            u64 da = 0, db = 0;
            da = f2(c01.x, zeA[0], da);  db = f2(c01.x, zeB[0], db);
            da = f2(c01.y, zeA[1], da);  db = f2(c01.y, zeB[1], db);
            da = f2(c23.x, zeA[2], da);  db = f2(c23.x, zeB[2], db);
            da = f2(c23.y, zeA[3], da);  db = f2(c23.y, zeB[3], db);
            float la, ha, lb, hb;
            upk(la, ha, da);
            upk(lb, hb, db);
            float dotA = la + ha;
            float dotB = lb + hb;
            int c = g * CG + cc;
            if (dotA > bestA) { bestA = dotA; biA = c; }   // strict >: first max wins
            if (dotB > bestB) { bestB = dotB; biB = c; }
        }
    }
    s_best[g * TILE + slot * 2]     = bestA;
    s_best[g * TILE + slot * 2 + 1] = bestB;
    s_bi[g * TILE + slot * 2]       = biA;
    s_bi[g * TILE + slot * 2 + 1]   = biB;
    __syncthreads();

    // combine argmax across groups (ascending g keeps first-index semantics)
    int fbiA, fbiB;
    {
        float vA = s_best[slot * 2], vB = s_best[slot * 2 + 1];
        fbiA = s_bi[slot * 2];  fbiB = s_bi[slot * 2 + 1];
#pragma unroll
        for (int gg = 1; gg < NG; gg++) {
            float wA = s_best[gg * TILE + slot * 2];
            float wB = s_best[gg * TILE + slot * 2 + 1];
            if (wA > vA) { vA = wA; fbiA = s_bi[gg * TILE + slot * 2]; }
            if (wB > vB) { vB = wB; fbiB = s_bi[gg * TILE + slot * 2 + 1]; }
        }
    }
    if (g == 0)
        __stcs((float2*)(out + OFF_IDX + (size_t)b * TT + t0),
               make_float2((float)fbiA, (float)fbiB));

    // gather raw codebook rows (L1/L2 resident)
    const float4* cb4 = (const float4*)cb;
    float4 qa0 = __ldg(cb4 + 2 * fbiA);
    float4 qa1 = __ldg(cb4 + 2 * fbiA + 1);
    float4 qb0 = __ldg(cb4 + 2 * fbiB);
    float4 qb1 = __ldg(cb4 + 2 * fbiB + 1);

    // loss scalar (all 8 groups duplicate -> x0.125 at the end)
    float ls = 0.f;
    {
        float zqa[CDIM] = {qa0.x, qa0.y, qa0.z, qa0.w, qa1.x, qa1.y, qa1.z, qa1.w};
        float zqb[CDIM] = {qb0.x, qb0.y, qb0.z, qb0.w, qb1.x, qb1.y, qb1.z, qb1.w};
#pragma unroll
        for (int j = 0; j < 4; j++) {
            float a0, a1, b0, b1;
            upk(a0, a1, zeA[j]);
            upk(b0, b1, zeB[j]);
            float d0 = a0 - zqa[2 * j], d1 = a1 - zqa[2 * j + 1];
            float d2 = b0 - zqb[2 * j], d3 = b1 - zqb[2 * j + 1];
            ls = fmaf(d0, d0, ls);
            ls = fmaf(d1, d1, ls);
            ls = fmaf(d2, d2, ls);
            ls = fmaf(d3, d3, ls);
        }
    }

    // ---- phase 3 (NO sync: wout resident, bias staged behind argmax sync) ----
    {
        u64 zqA[4] = { pk(qa0.x, qa0.y), pk(qa0.z, qa0.w), pk(qa1.x, qa1.y), pk(qa1.z, qa1.w) };
        u64 zqB[4] = { pk(qb0.x, qb0.y), pk(qb0.z, qb0.w), pk(qb1.x, qb1.y), pk(qb1.z, qb1.w) };
        const ulonglong2* wp = (const ulonglong2*)(s_wout + g * DG * CDIM);
        const float* bp = s_bias + g * DG;
        float* op = out + (size_t)b * (DD * TT) + (size_t)(g * DG) * TT + t0;
#pragma unroll 8
        for (int d = 0; d < DG; d++) {
            ulonglong2 w01 = wp[2 * d];        // warp-uniform LDS broadcast
            ulonglong2 w23 = wp[2 * d + 1];
            float bd = bp[d];
            u64 acA = 0, acB = 0;
            acA = f2(w01.x, zqA[0], acA);  acB = f2(w01.x, zqB[0], acB);
            acA = f2(w01.y, zqA[1], acA);  acB = f2(w01.y, zqB[1], acB);
            acA = f2(w23.x, zqA[2], acA);  acB = f2(w23.x, zqB[2], acB);
            acA = f2(w23.y, zqA[3], acA);  acB = f2(w23.y, zqB[3], acB);
            float la, ha, lb, hb;
            upk(la, ha, acA);
            upk(lb, hb, acB);
            __stcs((float2*)(op + (size_t)d * TT),
                   make_float2(la + ha + bd, lb + hb + bd));
        }
    }

    // ---- block loss reduction (deterministic) ----
#pragma unroll
    for (int m = 16; m > 0; m >>= 1)
        ls += __shfl_xor_sync(0xffffffffu, ls, m);
    if ((tid & 31) == 0) s_red[tid >> 5] = ls;
    __syncthreads();

    __shared__ bool s_amLast;
    if (tid == 0) {
        float tot = 0.f;
#pragma unroll
        for (int w = 0; w < NTHREADS / 32; w++) tot += s_red[w];
        g_losspart[blk] = tot * 0.125f;   // 8 groups duplicate each column
        __threadfence();
        unsigned int old = atomicAdd(&g_done, 1u);
        s_amLast = (old == GRID - 1);
    }
    __syncthreads();

    // last block: deterministic fixed-order final reduction
    if (s_amLast) {
        __threadfence();
        if (tid == 0) g_done = 0;          // self-reset for graph replay
        if (tid < BB) {
            const float* p = g_losspart + tid * TILES_PER_B;
            float s = 0.f;
            for (int i = 0; i < TILES_PER_B; i++) s += p[i];
            s *= (1.0f / (float)(CDIM * TT));
            out[OFF_CL + tid] = s;
            out[OFF_CB + tid] = s;
        }
    }
}

extern "C" void kernel_launch(void* const* d_in, const int* in_sizes, int n_in,
                              void* d_out, int out_size) {
    const float* z   = (const float*)d_in[0];
    const float* ipv = (const float*)d_in[1];
    const float* ipg = (const float*)d_in[2];
    const float* ipb = (const float*)d_in[3];
    const float* opv = (const float*)d_in[4];
    const float* opg = (const float*)d_in[5];
    const float* opb = (const float*)d_in[6];
    const float* cb  = (const float*)d_in[7];
    float* out = (float*)d_out;

    const int smem_bytes = 114752;   // 3 tables + 16K exchange + red
    cudaFuncSetAttribute(vq_main, cudaFuncAttributeMaxDynamicSharedMemorySize, smem_bytes);

    vq_prep<<<CDIM + 4, 256>>>(ipv, ipg, opv, opg, cb);
    vq_main<<<GRID, NTHREADS, smem_bytes>>>(z, ipb, opb, cb, out);
}

// round 10
// speedup vs baseline: 1.0439x; 1.0439x over previous
#include <cuda_runtime.h>
#include <math_constants.h>

// Problem constants
#define BB   16
#define DD   1024
#define TT   4096
#define CDIM 8
#define CSZ  1024

#define NTHREADS 512
#define NG   8                     // groups = 2 warps each (warp-uniform)
#define SLOTS 64                   // thread slots per group
#define TV   4                     // t-columns per thread (float4 path)
#define TILE (SLOTS * TV)          // 256 t per block
#define DG   (DD / NG)             // 128 d per group
#define CG   (CSZ / NG)            // 128 codes per group
#define TILES_PER_B (TT / TILE)    // 16
#define GRID (BB * TILES_PER_B)    // 256 (single wave at occ 2)

// Output layout (concatenated float32):
// out [B,D,T], commitment_loss [B], codebook_loss [B], indices [B,T], z_e [B,CD,T]
#define OFF_CL  (BB * DD * TT)
#define OFF_CB  (OFF_CL + BB)
#define OFF_IDX (OFF_CB + BB)
#define OFF_ZE  (OFF_IDX + BB * TT)

// Device-global scratch
__device__ float g_winT[DD * CDIM];   // in-proj weight transposed [d][k]
__device__ float g_wout[DD * CDIM];   // out-proj weight [d][k]
__device__ float g_cbn[CSZ * CDIM];   // normalized codebook [c][k]
__device__ float g_losspart[GRID];
__device__ unsigned int g_done;       // zero-init; self-resetting

// ---------------- f32x2 packed helpers ----------------
typedef unsigned long long u64;

__device__ __forceinline__ u64 pk(float lo, float hi) {
    u64 r; asm("mov.b64 %0, {%1, %2};" : "=l"(r) : "f"(lo), "f"(hi)); return r;
}
__device__ __forceinline__ void upk(float& lo, float& hi, u64 v) {
    asm("mov.b64 {%0, %1}, %2;" : "=f"(lo), "=f"(hi) : "l"(v));
}
__device__ __forceinline__ u64 f2(u64 a, u64 b, u64 c) {
    u64 d; asm("fma.rn.f32x2 %0, %1, %2, %3;" : "=l"(d) : "l"(a), "l"(b), "l"(c)); return d;
}
__device__ __forceinline__ u64 a2(u64 a, u64 b) {
    u64 d; asm("add.rn.f32x2 %0, %1, %2;" : "=l"(d) : "l"(a), "l"(b)); return d;
}

// Monotonic float->uint map: float order == unsigned order (no NaNs here).
// Packed key: [mapped value | ~index] -> u64 max == (max value, then min index)
__device__ __forceinline__ u64 packkey(float v, int idx) {
    unsigned int m = __float_as_uint(v);
    m ^= (m & 0x80000000u) ? 0xFFFFFFFFu : 0x80000000u;
    return ((u64)m << 32) | (u64)(~(unsigned int)idx);
}

// ---------------------------------------------------------------------------
// Prep: blocks 0..7 -> weight-norm in_proj row o (norm over D), transpose.
//       blocks 8..11 -> weight-norm out_proj rows + l2-normalized codebook.
// ---------------------------------------------------------------------------
__global__ void vq_prep(const float* __restrict__ ipv, const float* __restrict__ ipg,
                        const float* __restrict__ opv, const float* __restrict__ opg,
                        const float* __restrict__ cb) {
    if (blockIdx.x < CDIM) {
        int o = blockIdx.x;
        __shared__ float red[256];
        float s = 0.f;
        for (int d = threadIdx.x; d < DD; d += blockDim.x) {
            float x = ipv[o * DD + d];
            s = fmaf(x, x, s);
        }
        red[threadIdx.x] = s;
        __syncthreads();
        for (int off = 128; off > 0; off >>= 1) {
            if (threadIdx.x < off) red[threadIdx.x] += red[threadIdx.x + off];
            __syncthreads();
        }
        float scale = ipg[o] / sqrtf(red[0]);
        for (int d = threadIdx.x; d < DD; d += blockDim.x)
            g_winT[d * CDIM + o] = ipv[o * DD + d] * scale;
    } else {
        int i = (blockIdx.x - CDIM) * 256 + threadIdx.x;
        if (i < DD) {
            float vv[CDIM];
            float s = 0.f;
#pragma unroll
            for (int c = 0; c < CDIM; c++) { vv[c] = opv[i * CDIM + c]; s = fmaf(vv[c], vv[c], s); }
            float sc = opg[i] / sqrtf(s);
#pragma unroll
            for (int c = 0; c < CDIM; c++) g_wout[i * CDIM + c] = vv[c] * sc;
        }
        if (i < CSZ) {
            float vv[CDIM];
            float s = 0.f;
#pragma unroll
            for (int k = 0; k < CDIM; k++) { vv[k] = cb[i * CDIM + k]; s = fmaf(vv[k], vv[k], s); }
            float inv = 1.f / fmaxf(sqrtf(s), 1e-12f);
#pragma unroll
            for (int k = 0; k < CDIM; k++) g_cbn[i * CDIM + k] = vv[k] * inv;
        }
    }
}

// Dynamic smem layout (bytes):
//   s_winT [0,      32768)
//   s_cbn  [32768,  65536)
//   s_wout [65536,  98304)
//   s_ex   [98304, 114688)  16 KB: P1 exchange (4 rounds), then aliased as
//                           s_pack [NG][TILE] u64 for the argmax combine
//   s_red  [114688, 114752)
// Total 114752 B/block -> 2 blocks/SM.
// ---------------------------------------------------------------------------
__global__ void __launch_bounds__(NTHREADS, 2)
vq_main(const float* __restrict__ z,
        const float* __restrict__ in_b,
        const float* __restrict__ out_b,
        const float* __restrict__ cb,
        float* __restrict__ out) {
    extern __shared__ __align__(16) char smem[];
    float* s_winT = (float*)smem;
    float* s_cbn  = (float*)(smem + 32768);
    float* s_wout = (float*)(smem + 65536);
    u64*   s_ex   = (u64*)(smem + 98304);
    u64*   s_pack = (u64*)(smem + 98304);
    float* s_red  = (float*)(smem + 114688);

    const int tid  = threadIdx.x;
    const int g    = tid >> 6;          // group 0..7 (uniform across its 2 warps)
    const int slot = tid & (SLOTS - 1); // 0..63
    const int blk  = blockIdx.x;
    const int b    = blk / TILES_PER_B;
    const int t0   = (blk % TILES_PER_B) * TILE + slot * TV;

    // ---- stage ALL tables once (96 KB) ----
    {
        const float4* w1 = (const float4*)g_winT;
        const float4* w2 = (const float4*)g_cbn;
        const float4* w3 = (const float4*)g_wout;
        float4* d1 = (float4*)s_winT;
        float4* d2 = (float4*)s_cbn;
        float4* d3 = (float4*)s_wout;
        for (int i = tid; i < DD * CDIM / 4; i += NTHREADS) {
            d1[i] = w1[i];
            d2[i] = w2[i];
            d3[i] = w3[i];
        }
    }
    __syncthreads();

    // ---- phase 1: partial z_e over this group's 128 d's, 4 columns ----
    // ze[c][j]: column c (t0+c), k-pair j. Accumulators first, ze after combine.
    u64 ze[4][4];
#pragma unroll
    for (int c = 0; c < 4; c++)
#pragma unroll
        for (int j = 0; j < 4; j++) ze[c][j] = 0;
    {
        const float* zp = z + (size_t)b * (DD * TT) + (size_t)(g * DG) * TT + t0;
        const ulonglong2* wp = (const ulonglong2*)(s_winT + g * DG * CDIM);
#pragma unroll 4
        for (int d = 0; d < DG; d++) {
            float4 zv = __ldcs((const float4*)(zp + (size_t)d * TT));
            ulonglong2 w01 = wp[2 * d];        // warp-uniform LDS broadcast
            ulonglong2 w23 = wp[2 * d + 1];
            u64 z0 = pk(zv.x, zv.x);
            u64 z1 = pk(zv.y, zv.y);
            u64 z2 = pk(zv.z, zv.z);
            u64 z3 = pk(zv.w, zv.w);
            ze[0][0] = f2(w01.x, z0, ze[0][0]);  ze[0][1] = f2(w01.y, z0, ze[0][1]);
            ze[0][2] = f2(w23.x, z0, ze[0][2]);  ze[0][3] = f2(w23.y, z0, ze[0][3]);
            ze[1][0] = f2(w01.x, z1, ze[1][0]);  ze[1][1] = f2(w01.y, z1, ze[1][1]);
            ze[1][2] = f2(w23.x, z1, ze[1][2]);  ze[1][3] = f2(w23.y, z1, ze[1][3]);
            ze[2][0] = f2(w01.x, z2, ze[2][0]);  ze[2][1] = f2(w01.y, z2, ze[2][1]);
            ze[2][2] = f2(w23.x, z2, ze[2][2]);  ze[2][3] = f2(w23.y, z2, ze[2][3]);
            ze[3][0] = f2(w01.x, z3, ze[3][0]);  ze[3][1] = f2(w01.y, z3, ze[3][1]);
            ze[3][2] = f2(w23.x, z3, ze[3][2]);  ze[3][3] = f2(w23.y, z3, ze[3][3]);
        }
    }

    // ---- 4-round partial exchange (16 KB buffer), combine ascending g ----
    {
        const float2* bb = (const float2*)in_b;
#pragma unroll
        for (int j = 0; j < 4; j++) {
#pragma unroll
            for (int c = 0; c < 4; c++)
                s_ex[(c * NG + g) * SLOTS + slot] = ze[c][j];
            __syncthreads();
            float2 bj = __ldg(bb + j);
            u64 bp = pk(bj.x, bj.y);
#pragma unroll
            for (int c = 0; c < 4; c++) {
                u64 s = s_ex[(c * NG + 0) * SLOTS + slot];
#pragma unroll
                for (int gg = 1; gg < NG; gg++)
                    s = a2(s, s_ex[(c * NG + gg) * SLOTS + slot]);
                ze[c][j] = a2(s, bp);
            }
            __syncthreads();   // reads complete before buffer reuse
        }
    }

    // write z_e [B, CD, T]: group j (<4) writes rows 2j, 2j+1 as float4
    if (g < 4) {
        int j = g;
        float l0, h0, l1, h1, l2, h2, l3, h3;
        upk(l0, h0, ze[0][j]);
        upk(l1, h1, ze[1][j]);
        upk(l2, h2, ze[2][j]);
        upk(l3, h3, ze[3][j]);
        float* zeo = out + OFF_ZE + (size_t)b * (CDIM * TT) + t0;
        __stcs((float4*)(zeo + (size_t)(2 * j) * TT),     make_float4(l0, l1, l2, l3));
        __stcs((float4*)(zeo + (size_t)(2 * j + 1) * TT), make_float4(h0, h1, h2, h3));
    }

    // ---- phase 2: argmax over this group's 128 codes; 2 passes x 2 columns ----
#pragma unroll
    for (int pass = 0; pass < 2; pass++) {
        float b0 = -CUDART_INF_F, b1 = -CUDART_INF_F;
        int i0 = 0, i1 = 0;
        const float* cbase = s_cbn + g * CG * CDIM;
#pragma unroll 2
        for (int cc = 0; cc < CG; cc++) {
            const ulonglong2* r = (const ulonglong2*)(cbase + cc * CDIM);
            ulonglong2 c01 = r[0];   // warp-uniform LDS broadcast
            ulonglong2 c23 = r[1];
            u64 dx = 0, dy = 0;
            dx = f2(c01.x, ze[2 * pass][0], dx);      dy = f2(c01.x, ze[2 * pass + 1][0], dy);
            dx = f2(c01.y, ze[2 * pass][1], dx);      dy = f2(c01.y, ze[2 * pass + 1][1], dy);
            dx = f2(c23.x, ze[2 * pass][2], dx);      dy = f2(c23.x, ze[2 * pass + 1][2], dy);
            dx = f2(c23.y, ze[2 * pass][3], dx);      dy = f2(c23.y, ze[2 * pass + 1][3], dy);
            float lx, hx, ly, hy;
            upk(lx, hx, dx);
            upk(ly, hy, dy);
            float d0 = lx + hx;
            float d1 = ly + hy;
            int c = g * CG + cc;
            if (d0 > b0) { b0 = d0; i0 = c; }   // strict >: first max wins
            if (d1 > b1) { b1 = d1; i1 = c; }
        }
        s_pack[g * TILE + slot * 4 + 2 * pass]     = packkey(b0, i0);
        s_pack[g * TILE + slot * 4 + 2 * pass + 1] = packkey(b1, i1);
    }
    __syncthreads();

    // combine argmax across groups: u64 max == (max value, min index)
    int fbi[4];
#pragma unroll
    for (int c = 0; c < 4; c++) {
        u64 best = s_pack[0 * TILE + slot * 4 + c];
#pragma unroll
        for (int gg = 1; gg < NG; gg++) {
            u64 o = s_pack[gg * TILE + slot * 4 + c];
            if (o > best) best = o;
        }
        fbi[c] = (int)(~(unsigned int)best);
    }
    if (g == 0)
        __stcs((float4*)(out + OFF_IDX + (size_t)b * TT + t0),
               make_float4((float)fbi[0], (float)fbi[1], (float)fbi[2], (float)fbi[3]));

    // gather + pack zq per column, consuming ze for the loss as we go
    u64 zq[4][4];
    float ls = 0.f;
    {
        const float4* cb4 = (const float4*)cb;
#pragma unroll
        for (int c = 0; c < 4; c++) {
            float4 a = __ldg(cb4 + 2 * fbi[c]);
            float4 b4 = __ldg(cb4 + 2 * fbi[c] + 1);
            zq[c][0] = pk(a.x, a.y);
            zq[c][1] = pk(a.z, a.w);
            zq[c][2] = pk(b4.x, b4.y);
            zq[c][3] = pk(b4.z, b4.w);
            float lo, hi, d0, d1;
            upk(lo, hi, ze[c][0]); d0 = lo - a.x;  d1 = hi - a.y;
            ls = fmaf(d0, d0, ls); ls = fmaf(d1, d1, ls);
            upk(lo, hi, ze[c][1]); d0 = lo - a.z;  d1 = hi - a.w;
            ls = fmaf(d0, d0, ls); ls = fmaf(d1, d1, ls);
            upk(lo, hi, ze[c][2]); d0 = lo - b4.x; d1 = hi - b4.y;
            ls = fmaf(d0, d0, ls); ls = fmaf(d1, d1, ls);
            upk(lo, hi, ze[c][3]); d0 = lo - b4.z; d1 = hi - b4.w;
            ls = fmaf(d0, d0, ls); ls = fmaf(d1, d1, ls);
        }
    }

    // ---- phase 3 (NO sync: wout resident, bias via warp-uniform LDG) ----
    {
        const ulonglong2* wp = (const ulonglong2*)(s_wout + g * DG * CDIM);
        const float* bp = out_b + g * DG;
        float* op = out + (size_t)b * (DD * TT) + (size_t)(g * DG) * TT + t0;
#pragma unroll 4
        for (int d = 0; d < DG; d++) {
            ulonglong2 w01 = wp[2 * d];        // warp-uniform LDS broadcast
            ulonglong2 w23 = wp[2 * d + 1];
            float bd = __ldg(bp + d);
            u64 a0 = 0, a1 = 0, a2_ = 0, a3 = 0;
            a0 = f2(w01.x, zq[0][0], a0);  a1 = f2(w01.x, zq[1][0], a1);
            a2_ = f2(w01.x, zq[2][0], a2_); a3 = f2(w01.x, zq[3][0], a3);
            a0 = f2(w01.y, zq[0][1], a0);  a1 = f2(w01.y, zq[1][1], a1);
            a2_ = f2(w01.y, zq[2][1], a2_); a3 = f2(w01.y, zq[3][1], a3);
            a0 = f2(w23.x, zq[0][2], a0);  a1 = f2(w23.x, zq[1][2], a1);
            a2_ = f2(w23.x, zq[2][2], a2_); a3 = f2(w23.x, zq[3][2], a3);
            a0 = f2(w23.y, zq[0][3], a0);  a1 = f2(w23.y, zq[1][3], a1);
            a2_ = f2(w23.y, zq[2][3], a2_); a3 = f2(w23.y, zq[3][3], a3);
            float l0, h0, l1, h1, l2, h2, l3, h3;
            upk(l0, h0, a0);
            upk(l1, h1, a1);
            upk(l2, h2, a2_);
            upk(l3, h3, a3);
            __stcs((float4*)(op + (size_t)d * TT),
                   make_float4(l0 + h0 + bd, l1 + h1 + bd, l2 + h2 + bd, l3 + h3 + bd));
        }
    }

    // ---- block loss reduction (deterministic) ----
#pragma unroll
    for (int m = 16; m > 0; m >>= 1)
        ls += __shfl_xor_sync(0xffffffffu, ls, m);
    if ((tid & 31) == 0) s_red[tid >> 5] = ls;
    __syncthreads();

    __shared__ bool s_amLast;
    if (tid == 0) {
        float tot = 0.f;
#pragma unroll
        for (int w = 0; w < NTHREADS / 32; w++) tot += s_red[w];
        g_losspart[blk] = tot * 0.125f;   // 8 groups duplicate each column
        __threadfence();
        unsigned int old = atomicAdd(&g_done, 1u);
        s_amLast = (old == GRID - 1);
    }
    __syncthreads();

    // last block: deterministic fixed-order final reduction
    if (s_amLast) {
        __threadfence();
        if (tid == 0) g_done = 0;          // self-reset for graph replay
        if (tid < BB) {
            const float* p = g_losspart + tid * TILES_PER_B;
            float s = 0.f;
            for (int i = 0; i < TILES_PER_B; i++) s += p[i];
            s *= (1.0f / (float)(CDIM * TT));
            out[OFF_CL + tid] = s;
            out[OFF_CB + tid] = s;
        }
    }
}

extern "C" void kernel_launch(void* const* d_in, const int* in_sizes, int n_in,
                              void* d_out, int out_size) {
    const float* z   = (const float*)d_in[0];
    const float* ipv = (const float*)d_in[1];
    const float* ipg = (const float*)d_in[2];
    const float* ipb = (const float*)d_in[3];
    const float* opv = (const float*)d_in[4];
    const float* opg = (const float*)d_in[5];
    const float* opb = (const float*)d_in[6];
    const float* cb  = (const float*)d_in[7];
    float* out = (float*)d_out;

    const int smem_bytes = 114752;   // 3 tables + 16K exchange/pack + red
    cudaFuncSetAttribute(vq_main, cudaFuncAttributeMaxDynamicSharedMemorySize, smem_bytes);

    vq_prep<<<CDIM + 4, 256>>>(ipv, ipg, opv, opg, cb);
    vq_main<<<GRID, NTHREADS, smem_bytes>>>(z, ipb, opb, cb, out);
}